// round 2
// baseline (speedup 1.0000x reference)
#include <cuda_runtime.h>
#include <cuda_bf16.h>
#include <math.h>

// Problem constants
#define BB 32
#define NN 8192
#define DD 256
#define HH 8

typedef unsigned long long u64t;

// ------------------------- device scratch -------------------------
__device__ __align__(16) float g_Ws[HH * DD];            // prescaled by log2(e)
__device__ float g_c[HH];                                 // prescaled by log2(e)
__device__ __align__(16) float g_tpart[BB * 32 * HH * DD]; // [b][s][h][d]  (8 MB)
__device__ float g_zpart[BB * 32 * HH];
__device__ int g_mask_mode;

// ------------------------- f32x2 helpers -------------------------
__device__ __forceinline__ u64t pk(float lo, float hi) {
    u64t r; asm("mov.b64 %0,{%1,%2};" : "=l"(r) : "f"(lo), "f"(hi)); return r;
}
__device__ __forceinline__ void upk(u64t v, float& lo, float& hi) {
    asm("mov.b64 {%0,%1},%2;" : "=f"(lo), "=f"(hi) : "l"(v));
}
__device__ __forceinline__ u64t fma2(u64t a, u64t b, u64t c) {
    u64t d; asm("fma.rn.f32x2 %0,%1,%2,%3;" : "=l"(d) : "l"(a), "l"(b), "l"(c)); return d;
}
__device__ __forceinline__ u64t mul2(u64t a, u64t b) {
    u64t d; asm("mul.rn.f32x2 %0,%1,%2;" : "=l"(d) : "l"(a), "l"(b)); return d;
}
__device__ __forceinline__ u64t add2(u64t a, u64t b) {
    u64t d; asm("add.rn.f32x2 %0,%1,%2;" : "=l"(d) : "l"(a), "l"(b)); return d;
}
__device__ __forceinline__ float ex2f(float x) {
    float r; asm("ex2.approx.ftz.f32 %0,%1;" : "=f"(r) : "f"(x)); return r;
}
__device__ __forceinline__ u64t shfl64x(u64t v, int m) {
    return __shfl_xor_sync(0xffffffffu, v, m);
}

// ------------------------- kernel 0: detect mask dtype -------------------------
// float32 mask -> words 0x3F800000/0; int32 -> words 0/1; bool(uint8) -> byte-packed words > 1.
__global__ void detect_mask_kernel(const unsigned* __restrict__ mask) {
    __shared__ int sF, sBig;
    if (threadIdx.x == 0) { sF = 0; sBig = 0; }
    __syncthreads();
    int f = 0, big = 0;
    for (int i = threadIdx.x; i < 4096; i += blockDim.x) {
        unsigned x = mask[i];
        if (x == 0x3F800000u) f++;
        else if (x > 1u) big++;
    }
    atomicAdd(&sF, f); atomicAdd(&sBig, big);
    __syncthreads();
    if (threadIdx.x == 0)
        g_mask_mode = (sF > 1000) ? 2 : ((sBig > 100) ? 0 : 1);
}

__device__ __forceinline__ float load_maskv(const void* mask, int mode, size_t idx) {
    if (mode == 0) return ((const unsigned char*)mask)[idx] ? 1.0f : 0.0f;
    if (mode == 1) return ((const int*)mask)[idx] ? 1.0f : 0.0f;
    return ((const float*)mask)[idx];
}

// ------------------------- kernel 1: fold q through Wq and Wk -------------------------
__global__ void prep_kernel(const float* __restrict__ query, const float* __restrict__ Wq,
                            const float* __restrict__ bq, const float* __restrict__ Wk,
                            const float* __restrict__ bk) {
    __shared__ float qh[DD];
    const int t = threadIdx.x; // 256 threads
    float acc = bq[t];
    #pragma unroll 8
    for (int i = 0; i < DD; i++) acc += query[i] * Wq[(size_t)t * DD + i];
    qh[t] = acc * 0.17677669529663687f; // 1/sqrt(32)
    __syncthreads();
    const float LOG2E = 1.4426950408889634f;
    #pragma unroll
    for (int h = 0; h < HH; h++) {
        float s = 0.f;
        #pragma unroll 8
        for (int dh = 0; dh < 32; dh++)
            s += qh[h * 32 + dh] * Wk[(size_t)(h * 32 + dh) * DD + t];
        g_Ws[h * DD + t] = s * LOG2E;
    }
    if (t < HH) {
        float s = 0.f;
        #pragma unroll
        for (int dh = 0; dh < 32; dh++) s += qh[t * 32 + dh] * bk[t * 32 + dh];
        g_c[t] = s * LOG2E;
    }
}

// ------------------------- kernel 2: fused scores + online weighted accumulation -------------------------
// Grid (32 segments, 32 batches), 256 threads. Warp-per-token, lane owns 8 dims as 4 f32x2 pairs.
__global__ void __launch_bounds__(256, 1) attn_main_kernel(const float* __restrict__ tokens,
                                                           const void* __restrict__ mask) {
    const int s = blockIdx.x, b = blockIdx.y;
    const int tid = threadIdx.x, w = tid >> 5, lane = tid & 31;

    __shared__ float sacc[HH * DD];
    __shared__ float szz[HH];
    for (int i = tid; i < HH * DD; i += 256) sacc[i] = 0.f;
    if (tid < HH) szz[tid] = 0.f;

    // Ws (log2e-prescaled) into registers as f32x2 pairs
    u64t Ws2[HH][4];
    #pragma unroll
    for (int h = 0; h < HH; h++) {
        float4 a = *(const float4*)(g_Ws + h * DD + 4 * lane);
        float4 c = *(const float4*)(g_Ws + h * DD + 128 + 4 * lane);
        Ws2[h][0] = pk(a.x, a.y);  Ws2[h][1] = pk(a.z, a.w);
        Ws2[h][2] = pk(c.x, c.y);  Ws2[h][3] = pk(c.z, c.w);
    }
    u64t c2[4];
    #pragma unroll
    for (int j = 0; j < 4; j++) c2[j] = pk(g_c[2 * j], g_c[2 * j + 1]);
    const u64t dead2 = pk(-100000.0f, -100000.0f);

    u64t acc2[HH][4];
    #pragma unroll
    for (int h = 0; h < HH; h++)
        #pragma unroll
        for (int j = 0; j < 4; j++) acc2[h][j] = 0ull;
    u64t z2[4] = {0ull, 0ull, 0ull, 0ull};

    const int mode = g_mask_mode;
    const size_t rowbase = (size_t)b * NN + (size_t)s * 256 + w;
    const float4* tokp = (const float4*)tokens;

    // prefetch first token
    float4 v0 = tokp[(rowbase) * 64 + lane];
    float4 v1 = tokp[(rowbase) * 64 + 32 + lane];
    float mv = load_maskv(mask, mode, rowbase);

    #pragma unroll 1
    for (int it = 0; it < 32; it++) {
        float4 nv0, nv1; float nmv = 0.f;
        if (it < 31) {
            size_t nr = rowbase + 8 * (it + 1);
            nv0 = tokp[nr * 64 + lane];
            nv1 = tokp[nr * 64 + 32 + lane];
            nmv = load_maskv(mask, mode, nr);
        } else { nv0 = v0; nv1 = v1; }

        u64t tk[4] = { pk(v0.x, v0.y), pk(v0.z, v0.w), pk(v1.x, v1.y), pk(v1.z, v1.w) };

        // per-lane partial head scores (packed over dim pairs)
        float sh[HH];
        #pragma unroll
        for (int h = 0; h < HH; h++) {
            u64t p = mul2(tk[0], Ws2[h][0]);
            p = fma2(tk[1], Ws2[h][1], p);
            p = fma2(tk[2], Ws2[h][2], p);
            p = fma2(tk[3], Ws2[h][3], p);
            float lo, hi; upk(p, lo, hi);
            sh[h] = lo + hi;
        }
        // pack head pairs and butterfly-reduce (broadcast full sums to all lanes)
        u64t r0 = pk(sh[0], sh[1]), r1 = pk(sh[2], sh[3]);
        u64t r2 = pk(sh[4], sh[5]), r3 = pk(sh[6], sh[7]);
        #pragma unroll
        for (int m = 16; m >= 1; m >>= 1) {
            r0 = add2(r0, shfl64x(r0, m));
            r1 = add2(r1, shfl64x(r1, m));
            r2 = add2(r2, shfl64x(r2, m));
            r3 = add2(r3, shfl64x(r3, m));
        }
        // bias (+ mask via -inf-equivalent), then exp2
        const bool valid = (mv != 0.0f);
        r0 = add2(r0, valid ? c2[0] : dead2);
        r1 = add2(r1, valid ? c2[1] : dead2);
        r2 = add2(r2, valid ? c2[2] : dead2);
        r3 = add2(r3, valid ? c2[3] : dead2);

        float e[HH];
        { float lo, hi; upk(r0, lo, hi); e[0] = ex2f(lo); e[1] = ex2f(hi); }
        { float lo, hi; upk(r1, lo, hi); e[2] = ex2f(lo); e[3] = ex2f(hi); }
        { float lo, hi; upk(r2, lo, hi); e[4] = ex2f(lo); e[5] = ex2f(hi); }
        { float lo, hi; upk(r3, lo, hi); e[6] = ex2f(lo); e[7] = ex2f(hi); }

        z2[0] = add2(z2[0], pk(e[0], e[1]));
        z2[1] = add2(z2[1], pk(e[2], e[3]));
        z2[2] = add2(z2[2], pk(e[4], e[5]));
        z2[3] = add2(z2[3], pk(e[6], e[7]));

        #pragma unroll
        for (int h = 0; h < HH; h++) {
            u64t eb = pk(e[h], e[h]);
            acc2[h][0] = fma2(tk[0], eb, acc2[h][0]);
            acc2[h][1] = fma2(tk[1], eb, acc2[h][1]);
            acc2[h][2] = fma2(tk[2], eb, acc2[h][2]);
            acc2[h][3] = fma2(tk[3], eb, acc2[h][3]);
        }

        v0 = nv0; v1 = nv1; mv = nmv;
    }

    __syncthreads();
    // deterministic staggered cross-warp reduction into smem
    for (int r = 0; r < 8; r++) {
        if (w == r) {
            #pragma unroll
            for (int h = 0; h < HH; h++) {
                #pragma unroll
                for (int j = 0; j < 4; j++) {
                    float lo, hi; upk(acc2[h][j], lo, hi);
                    int d = (j < 2) ? (4 * lane + 2 * j) : (128 + 4 * lane + 2 * (j - 2));
                    sacc[h * DD + d]     += lo;
                    sacc[h * DD + d + 1] += hi;
                }
            }
            if (lane == 0) {
                float lo, hi;
                upk(z2[0], lo, hi); szz[0] += lo; szz[1] += hi;
                upk(z2[1], lo, hi); szz[2] += lo; szz[3] += hi;
                upk(z2[2], lo, hi); szz[4] += lo; szz[5] += hi;
                upk(z2[3], lo, hi); szz[6] += lo; szz[7] += hi;
            }
        }
        __syncthreads();
    }

    const size_t part = (size_t)(b * 32 + s);
    for (int i = tid; i < HH * DD; i += 256) g_tpart[part * (HH * DD) + i] = sacc[i];
    if (tid < HH) g_zpart[part * HH + tid] = szz[tid];
}

// ------------------------- kernel 3: per-batch epilogue -------------------------
__global__ void __launch_bounds__(256) epilogue_kernel(
    const float* __restrict__ Wv, const float* __restrict__ bv,
    const float* __restrict__ Wo, const float* __restrict__ bo,
    const float* __restrict__ ln1g, const float* __restrict__ ln1b,
    const float* __restrict__ W1, const float* __restrict__ b1,
    const float* __restrict__ W2, const float* __restrict__ b2,
    const float* __restrict__ ln2g, const float* __restrict__ ln2b,
    float* __restrict__ out)
{
    const int b = blockIdx.x;
    const int t = threadIdx.x;

    __shared__ float tb[HH * DD];   // tbar
    __shared__ float sz[HH];
    __shared__ float sctx[DD];
    __shared__ float sx[DD];        // scratch for LN stats
    __shared__ float sp[DD];        // pooled
    __shared__ float shb[4 * DD];   // gelu hidden

    // 1) reduce partials over segments, normalize by z
    float a[HH];
    #pragma unroll
    for (int h = 0; h < HH; h++) {
        float acc = 0.f;
        #pragma unroll 4
        for (int s = 0; s < 32; s++)
            acc += g_tpart[(size_t)(b * 32 + s) * (HH * DD) + h * DD + t];
        a[h] = acc;
    }
    if (t < HH) {
        float z = 0.f;
        #pragma unroll 4
        for (int s = 0; s < 32; s++) z += g_zpart[(b * 32 + s) * HH + t];
        sz[t] = z;
    }
    __syncthreads();
    #pragma unroll
    for (int h = 0; h < HH; h++) tb[h * DD + t] = a[h] / sz[h];
    __syncthreads();

    // 2) ctx[j] = bv[j] + tbar[h(j),:] . Wv[j,:]
    {
        const int h = t >> 5;
        const float4* wr = (const float4*)(Wv + (size_t)t * DD);
        const float4* tr = (const float4*)(tb + h * DD);
        float s0 = 0.f, s1 = 0.f, s2 = 0.f, s3 = 0.f;
        #pragma unroll 8
        for (int i = 0; i < 64; i++) {
            float4 wv4 = wr[i]; float4 tv4 = tr[i];
            s0 += wv4.x * tv4.x; s1 += wv4.y * tv4.y;
            s2 += wv4.z * tv4.z; s3 += wv4.w * tv4.w;
        }
        sctx[t] = bv[t] + (s0 + s1) + (s2 + s3);
    }
    __syncthreads();

    // 3) attn_out = ctx @ Wo^T + bo, then LN1
    float ao;
    {
        const float4* wr = (const float4*)(Wo + (size_t)t * DD);
        const float4* cr = (const float4*)sctx;
        float s0 = 0.f, s1 = 0.f, s2 = 0.f, s3 = 0.f;
        #pragma unroll 8
        for (int i = 0; i < 64; i++) {
            float4 wv4 = wr[i]; float4 cv4 = cr[i];
            s0 += wv4.x * cv4.x; s1 += wv4.y * cv4.y;
            s2 += wv4.z * cv4.z; s3 += wv4.w * cv4.w;
        }
        ao = bo[t] + (s0 + s1) + (s2 + s3);
    }
    sx[t] = ao;
    __syncthreads();
    {
        float s1v = 0.f, s2v = 0.f;
        #pragma unroll 8
        for (int i = 0; i < DD; i++) { float x = sx[i]; s1v += x; s2v += x * x; }
        float m = s1v * (1.0f / DD);
        float var = s2v * (1.0f / DD) - m * m;
        float pooled = (ao - m) * rsqrtf(var + 1e-5f) * ln1g[t] + ln1b[t];
        sp[t] = pooled;
    }
    __syncthreads();

    // 5) hidden = gelu(pooled @ W1^T + b1), exact erf gelu
    #pragma unroll
    for (int q = 0; q < 4; q++) {
        const int k = q * DD + t;
        const float4* wr = (const float4*)(W1 + (size_t)k * DD);
        const float4* pr = (const float4*)sp;
        float s0 = 0.f, s1 = 0.f, s2 = 0.f, s3 = 0.f;
        #pragma unroll 8
        for (int i = 0; i < 64; i++) {
            float4 wv4 = wr[i]; float4 pv4 = pr[i];
            s0 += wv4.x * pv4.x; s1 += wv4.y * pv4.y;
            s2 += wv4.z * pv4.z; s3 += wv4.w * pv4.w;
        }
        float hh = b1[k] + (s0 + s1) + (s2 + s3);
        shb[k] = 0.5f * hh * (1.0f + erff(hh * 0.70710678118654752f));
    }
    __syncthreads();

    // 6) mlp = hidden @ W2^T + b2; residual; LN2
    float r;
    {
        const float4* wr = (const float4*)(W2 + (size_t)t * (4 * DD));
        const float4* hr = (const float4*)shb;
        float s0 = 0.f, s1 = 0.f, s2 = 0.f, s3 = 0.f;
        #pragma unroll 8
        for (int i = 0; i < 256; i++) {
            float4 wv4 = wr[i]; float4 hv4 = hr[i];
            s0 += wv4.x * hv4.x; s1 += wv4.y * hv4.y;
            s2 += wv4.z * hv4.z; s3 += wv4.w * hv4.w;
        }
        r = b2[t] + (s0 + s1) + (s2 + s3) + sp[t];
    }
    sx[t] = r;
    __syncthreads();
    {
        float s1v = 0.f, s2v = 0.f;
        #pragma unroll 8
        for (int i = 0; i < DD; i++) { float x = sx[i]; s1v += x; s2v += x * x; }
        float m = s1v * (1.0f / DD);
        float var = s2v * (1.0f / DD) - m * m;
        out[b * DD + t] = (r - m) * rsqrtf(var + 1e-5f) * ln2g[t] + ln2b[t];
    }
}

// ------------------------- launch -------------------------
extern "C" void kernel_launch(void* const* d_in, const int* in_sizes, int n_in,
                              void* d_out, int out_size) {
    const float* tokens = (const float*)d_in[0];
    const void*  mask   = d_in[1];
    const float* query  = (const float*)d_in[2];
    const float* Wq     = (const float*)d_in[3];
    const float* bq     = (const float*)d_in[4];
    const float* Wk     = (const float*)d_in[5];
    const float* bk     = (const float*)d_in[6];
    const float* Wv     = (const float*)d_in[7];
    const float* bv     = (const float*)d_in[8];
    const float* Wo     = (const float*)d_in[9];
    const float* bo     = (const float*)d_in[10];
    const float* ln1g   = (const float*)d_in[11];
    const float* ln1b   = (const float*)d_in[12];
    const float* W1     = (const float*)d_in[13];
    const float* b1     = (const float*)d_in[14];
    const float* W2     = (const float*)d_in[15];
    const float* b2     = (const float*)d_in[16];
    const float* ln2g   = (const float*)d_in[17];
    const float* ln2b   = (const float*)d_in[18];
    float* out = (float*)d_out;

    detect_mask_kernel<<<1, 256>>>((const unsigned*)mask);
    prep_kernel<<<1, 256>>>(query, Wq, bq, Wk, bk);
    attn_main_kernel<<<dim3(32, 32), 256>>>(tokens, mask);
    epilogue_kernel<<<32, 256>>>(Wv, bv, Wo, bo, ln1g, ln1b, W1, b1, W2, b2, ln2g, ln2b, out);
}

// round 4
// speedup vs baseline: 2.2937x; 2.2937x over previous
#include <cuda_runtime.h>
#include <cuda_bf16.h>
#include <math.h>

#define BB 32
#define NN 8192
#define DD 256
#define HH 8

typedef unsigned long long u64t;

// ------------------------- device scratch -------------------------
__device__ __align__(16) float g_Ws[HH * DD];              // prescaled by log2(e)
__device__ float g_c[HH];                                   // prescaled by log2(e)
__device__ __align__(16) float g_qh[DD];
__device__ __align__(16) float g_tpart[BB * 32 * HH * DD];  // 8 MB
__device__ float g_zpart[BB * 32 * HH];
__device__ float g_zinv[BB * HH];
__device__ __align__(16) float g_tbar[BB * HH * DD];
__device__ __align__(16) float g_ctx[BB * DD];
__device__ __align__(16) float g_ao[BB * DD];
__device__ __align__(16) float g_pl[BB * DD];
__device__ __align__(16) float g_hid[BB * 4 * DD];
__device__ __align__(16) float g_res[BB * DD];
__device__ int g_mask_mode;

// ------------------------- f32x2 helpers -------------------------
__device__ __forceinline__ u64t pk(float lo, float hi) {
    u64t r; asm("mov.b64 %0,{%1,%2};" : "=l"(r) : "f"(lo), "f"(hi)); return r;
}
__device__ __forceinline__ void upk(u64t v, float& lo, float& hi) {
    asm("mov.b64 {%0,%1},%2;" : "=f"(lo), "=f"(hi) : "l"(v));
}
__device__ __forceinline__ u64t fma2(u64t a, u64t b, u64t c) {
    u64t d; asm("fma.rn.f32x2 %0,%1,%2,%3;" : "=l"(d) : "l"(a), "l"(b), "l"(c)); return d;
}
__device__ __forceinline__ u64t mul2(u64t a, u64t b) {
    u64t d; asm("mul.rn.f32x2 %0,%1,%2;" : "=l"(d) : "l"(a), "l"(b)); return d;
}
__device__ __forceinline__ u64t add2(u64t a, u64t b) {
    u64t d; asm("add.rn.f32x2 %0,%1,%2;" : "=l"(d) : "l"(a), "l"(b)); return d;
}
__device__ __forceinline__ float ex2f(float x) {
    float r; asm("ex2.approx.ftz.f32 %0,%1;" : "=f"(r) : "f"(x)); return r;
}
__device__ __forceinline__ u64t shfl64x(u64t v, int m) {
    return __shfl_xor_sync(0xffffffffu, v, m);
}

// ------------------------- mask handling -------------------------
__global__ void detect_mask_kernel(const unsigned* __restrict__ mask) {
    __shared__ int sF, sBig;
    if (threadIdx.x == 0) { sF = 0; sBig = 0; }
    __syncthreads();
    int f = 0, big = 0;
    for (int i = threadIdx.x; i < 4096; i += blockDim.x) {
        unsigned x = mask[i];
        if (x == 0x3F800000u) f++;
        else if (x > 1u) big++;
    }
    atomicAdd(&sF, f); atomicAdd(&sBig, big);
    __syncthreads();
    if (threadIdx.x == 0)
        g_mask_mode = (sF > 1000) ? 2 : ((sBig > 100) ? 0 : 1);
}

__device__ __forceinline__ float load_maskv(const void* mask, int mode, size_t idx) {
    if (mode == 0) return ((const unsigned char*)mask)[idx] ? 1.0f : 0.0f;
    if (mode == 1) return ((const int*)mask)[idx] ? 1.0f : 0.0f;
    return ((const float*)mask)[idx];
}

// ------------------------- warp dot helpers -------------------------
__device__ __forceinline__ float wdot256(const float* __restrict__ W,
                                         const float* __restrict__ x, int lane) {
    float4 w0 = *(const float4*)(W + 4 * lane);
    float4 w1 = *(const float4*)(W + 128 + 4 * lane);
    float4 x0 = *(const float4*)(x + 4 * lane);
    float4 x1 = *(const float4*)(x + 128 + 4 * lane);
    float s = w0.x * x0.x + w0.y * x0.y + w0.z * x0.z + w0.w * x0.w
            + w1.x * x1.x + w1.y * x1.y + w1.z * x1.z + w1.w * x1.w;
    #pragma unroll
    for (int m = 16; m; m >>= 1) s += __shfl_xor_sync(0xffffffffu, s, m);
    return s;
}
__device__ __forceinline__ float wdot1024(const float* __restrict__ W,
                                          const float* __restrict__ x, int lane) {
    float s = 0.f;
    #pragma unroll
    for (int c = 0; c < 8; c++) {
        float4 wv = *(const float4*)(W + c * 128 + 4 * lane);
        float4 xv = *(const float4*)(x + c * 128 + 4 * lane);
        s += wv.x * xv.x + wv.y * xv.y + wv.z * xv.z + wv.w * xv.w;
    }
    #pragma unroll
    for (int m = 16; m; m >>= 1) s += __shfl_xor_sync(0xffffffffu, s, m);
    return s;
}

// ------------------------- prep: qh then Ws -------------------------
__global__ void prep_qh_kernel(const float* __restrict__ query, const float* __restrict__ Wq,
                               const float* __restrict__ bq) {
    const int lane = threadIdx.x & 31;
    const int j = blockIdx.x * 8 + (threadIdx.x >> 5);
    float v = bq[j] + wdot256(Wq + (size_t)j * DD, query, lane);
    if (lane == 0) g_qh[j] = v * 0.17677669529663687f; // 1/sqrt(32)
}

__global__ void prep_ws_kernel(const float* __restrict__ Wk, const float* __restrict__ bk) {
    __shared__ float q[DD];
    const int t = threadIdx.x;
    q[t] = g_qh[t];
    __syncthreads();
    const float LOG2E = 1.4426950408889634f;
    #pragma unroll
    for (int h = 0; h < HH; h++) {
        float s = 0.f;
        #pragma unroll 8
        for (int dh = 0; dh < 32; dh++)
            s += q[h * 32 + dh] * Wk[(size_t)(h * 32 + dh) * DD + t];
        g_Ws[h * DD + t] = s * LOG2E;
    }
    if (t < HH) {
        float s = 0.f;
        #pragma unroll
        for (int dh = 0; dh < 32; dh++) s += q[t * 32 + dh] * bk[t * 32 + dh];
        g_c[t] = s * LOG2E;
    }
}

// ------------------------- main fused attention pass -------------------------
// Grid (32 seg, 32 batch) x 256 threads. Warp-per-token-stream; tokens in groups
// of 4; score reduction via smem transpose (no butterflies, 0.5 MUFU/token).
__global__ void __launch_bounds__(256, 1) attn_main_kernel(const float* __restrict__ tokens,
                                                           const void* __restrict__ mask) {
    const int s = blockIdx.x, b = blockIdx.y;
    const int tid = threadIdx.x, w = tid >> 5, lane = tid & 31;

    __shared__ __align__(16) unsigned char smraw[36608];
    u64t* spart = (u64t*)smraw;                 // [w*528 + r*33 + lane], r = it*4+p
    u64t* sebuf = (u64t*)(smraw + 33792);       // [w*32 + it*8 + h] duplicated e
    float* smv  = (float*)(smraw + 35840);      // [w*4 + it]
    float* szb  = (float*)(smraw + 35968);      // [w*8 + h]
    u64t* sred  = (u64t*)smraw;                 // tail reuse (32 KB < 33792)

    // Ws (log2e-prescaled) into registers as f32x2 pairs
    u64t Ws2[HH][4];
    #pragma unroll
    for (int h = 0; h < HH; h++) {
        float4 a = *(const float4*)(g_Ws + h * DD + 4 * lane);
        float4 c = *(const float4*)(g_Ws + h * DD + 128 + 4 * lane);
        Ws2[h][0] = pk(a.x, a.y);  Ws2[h][1] = pk(a.z, a.w);
        Ws2[h][2] = pk(c.x, c.y);  Ws2[h][3] = pk(c.z, c.w);
    }
    const int p = lane & 3;
    const u64t c2l = pk(g_c[2 * p], g_c[2 * p + 1]);

    u64t acc2[HH][4];
    #pragma unroll
    for (int h = 0; h < HH; h++)
        #pragma unroll
        for (int j = 0; j < 4; j++) acc2[h][j] = 0ull;
    u64t zloc = 0ull;

    const int mode = g_mask_mode;
    const size_t rowbase = (size_t)b * NN + (size_t)s * 256 + w;
    const float4* tokp = (const float4*)tokens;

    // preload group 0
    float4 nv[4][2];
    #pragma unroll
    for (int it = 0; it < 4; it++) {
        size_t r = rowbase + 8 * it;
        nv[it][0] = tokp[r * 64 + lane];
        nv[it][1] = tokp[r * 64 + 32 + lane];
    }
    u64t tk[4][4];
    #pragma unroll
    for (int it = 0; it < 4; it++) {
        tk[it][0] = pk(nv[it][0].x, nv[it][0].y);
        tk[it][1] = pk(nv[it][0].z, nv[it][0].w);
        tk[it][2] = pk(nv[it][1].x, nv[it][1].y);
        tk[it][3] = pk(nv[it][1].z, nv[it][1].w);
    }

    #pragma unroll 1
    for (int g = 0; g < 8; g++) {
        // prefetch next group
        if (g < 7) {
            #pragma unroll
            for (int it = 0; it < 4; it++) {
                size_t r = rowbase + 8 * (4 * (g + 1) + it);
                nv[it][0] = tokp[r * 64 + lane];
                nv[it][1] = tokp[r * 64 + 32 + lane];
            }
        }
        // mask values for this group (lanes 0..3)
        if (lane < 4)
            smv[w * 4 + lane] = load_maskv(mask, mode, rowbase + 8 * (4 * g + lane));

        // Stage A: per-lane head-pair partials -> smem (transposed rows)
        #pragma unroll
        for (int it = 0; it < 4; it++) {
            float sh[HH];
            #pragma unroll
            for (int h = 0; h < HH; h++) {
                u64t pp = mul2(tk[it][0], Ws2[h][0]);
                pp = fma2(tk[it][1], Ws2[h][1], pp);
                pp = fma2(tk[it][2], Ws2[h][2], pp);
                pp = fma2(tk[it][3], Ws2[h][3], pp);
                float lo, hi; upk(pp, lo, hi);
                sh[h] = lo + hi;
            }
            const int rb = w * 528 + (it * 4) * 33 + lane;
            spart[rb]          = pk(sh[0], sh[1]);
            spart[rb + 33]     = pk(sh[2], sh[3]);
            spart[rb + 66]     = pk(sh[4], sh[5]);
            spart[rb + 99]     = pk(sh[6], sh[7]);
        }
        __syncwarp();

        // Stage B: 16 lanes each reduce one (token,head-pair) row, exp, mask
        if (lane < 16) {
            const int it = lane >> 2;
            const u64t* row = spart + w * 528 + lane * 33;
            u64t s0 = row[0], s1 = row[1], s2 = row[2], s3 = row[3];
            #pragma unroll
            for (int k = 4; k < 32; k += 4) {
                s0 = add2(s0, row[k]);     s1 = add2(s1, row[k + 1]);
                s2 = add2(s2, row[k + 2]); s3 = add2(s3, row[k + 3]);
            }
            u64t ss = add2(add2(s0, s1), add2(s2, s3));
            ss = add2(ss, c2l);
            float lo, hi; upk(ss, lo, hi);
            const float mv = smv[w * 4 + it];
            const float e0 = ex2f(lo) * mv;
            const float e1 = ex2f(hi) * mv;
            zloc = add2(zloc, pk(e0, e1));
            sebuf[w * 32 + it * 8 + 2 * p]     = pk(e0, e0);
            sebuf[w * 32 + it * 8 + 2 * p + 1] = pk(e1, e1);
        }
        __syncwarp();

        // Stage C: weighted accumulation (tokens still in registers)
        #pragma unroll
        for (int it = 0; it < 4; it++) {
            #pragma unroll
            for (int h = 0; h < HH; h++) {
                const u64t eb = sebuf[w * 32 + it * 8 + h];
                acc2[h][0] = fma2(tk[it][0], eb, acc2[h][0]);
                acc2[h][1] = fma2(tk[it][1], eb, acc2[h][1]);
                acc2[h][2] = fma2(tk[it][2], eb, acc2[h][2]);
                acc2[h][3] = fma2(tk[it][3], eb, acc2[h][3]);
            }
        }
        // rotate prefetched tokens in
        if (g < 7) {
            #pragma unroll
            for (int it = 0; it < 4; it++) {
                tk[it][0] = pk(nv[it][0].x, nv[it][0].y);
                tk[it][1] = pk(nv[it][0].z, nv[it][0].w);
                tk[it][2] = pk(nv[it][1].x, nv[it][1].y);
                tk[it][3] = pk(nv[it][1].z, nv[it][1].w);
            }
        }
        __syncwarp();
    }

    // z: fold it-slots (lanes p, p+4, p+8, p+12 share head pair p)
    zloc = add2(zloc, shfl64x(zloc, 4));
    zloc = add2(zloc, shfl64x(zloc, 8));
    zloc = add2(zloc, shfl64x(zloc, 16));
    if (lane < 4) {
        float lo, hi; upk(zloc, lo, hi);
        szb[w * 8 + 2 * p]     = lo;
        szb[w * 8 + 2 * p + 1] = hi;
    }
    __syncthreads();

    // parallel cross-warp accumulator reduction (two halves to fit smem)
    const int part = b * 32 + s;
    u64t* tpart2 = (u64t*)g_tpart;
    #pragma unroll
    for (int half = 0; half < 2; half++) {
        #pragma unroll
        for (int hl = 0; hl < 4; hl++) {
            #pragma unroll
            for (int j = 0; j < 4; j++) {
                const int pairpos = (j < 2) ? (2 * lane + j) : (64 + 2 * lane + (j - 2));
                sred[w * 512 + hl * 128 + pairpos] = acc2[half * 4 + hl][j];
            }
        }
        __syncthreads();
        #pragma unroll
        for (int rq = 0; rq < 2; rq++) {
            const int q = tid + rq * 256;
            u64t ssum = sred[q];
            #pragma unroll
            for (int ww = 1; ww < 8; ww++) ssum = add2(ssum, sred[ww * 512 + q]);
            const int hl = q >> 7, pairpos = q & 127;
            tpart2[(size_t)part * 1024 + (size_t)(half * 4 + hl) * 128 + pairpos] = ssum;
        }
        __syncthreads();
    }
    if (tid < 8) {
        float zz = 0.f;
        #pragma unroll
        for (int ww = 0; ww < 8; ww++) zz += szb[ww * 8 + tid];
        g_zpart[part * 8 + tid] = zz;
    }
}

// ------------------------- epilogue kernels (wide, parallel) -------------------------
__global__ void ep_z_kernel() {
    const int tid = threadIdx.x;          // 256: b = tid>>3, h = tid&7
    const int b = tid >> 3, h = tid & 7;
    float z = 0.f;
    #pragma unroll 4
    for (int s = 0; s < 32; s++) z += g_zpart[(b * 32 + s) * 8 + h];
    g_zinv[tid] = 1.0f / z;
}

__global__ void ep_reduce_kernel() {
    const int idx = blockIdx.x * 256 + threadIdx.x; // 32768 float2 outputs
    const int b = idx >> 10, j2 = idx & 1023;
    const int h = j2 >> 7;
    const float2* tp = (const float2*)g_tpart;
    float ax = 0.f, ay = 0.f;
    #pragma unroll 4
    for (int s = 0; s < 32; s++) {
        float2 v = tp[(size_t)(b * 32 + s) * 1024 + j2];
        ax += v.x; ay += v.y;
    }
    const float zi = g_zinv[b * 8 + h];
    ((float2*)g_tbar)[(size_t)b * 1024 + j2] = make_float2(ax * zi, ay * zi);
}

__global__ void ep_ctx_kernel(const float* __restrict__ Wv, const float* __restrict__ bv) {
    const int lane = threadIdx.x & 31;
    const int gw = blockIdx.x * 8 + (threadIdx.x >> 5);
    const int b = gw & 31, j = gw >> 5;
    float v = bv[j] + wdot256(Wv + (size_t)j * DD, g_tbar + (size_t)b * 2048 + (j >> 5) * 256, lane);
    if (lane == 0) g_ctx[b * DD + j] = v;
}

__global__ void ep_attnout_kernel(const float* __restrict__ Wo, const float* __restrict__ bo) {
    const int lane = threadIdx.x & 31;
    const int gw = blockIdx.x * 8 + (threadIdx.x >> 5);
    const int b = gw & 31, t = gw >> 5;
    float v = bo[t] + wdot256(Wo + (size_t)t * DD, g_ctx + (size_t)b * DD, lane);
    if (lane == 0) g_ao[b * DD + t] = v;
}

// LN1: reads g_ao (device symbol, device-side), writes g_pl
__global__ void ep_ln1_kernel(const float* __restrict__ gg, const float* __restrict__ bb) {
    const int b = blockIdx.x, t = threadIdx.x;
    __shared__ float sx[DD];
    const float v = g_ao[b * DD + t];
    sx[t] = v;
    __syncthreads();
    float s1 = 0.f, s2 = 0.f;
    #pragma unroll 8
    for (int i = 0; i < DD; i++) { float x = sx[i]; s1 += x; s2 += x * x; }
    const float m = s1 * (1.0f / DD);
    const float var = s2 * (1.0f / DD) - m * m;
    g_pl[b * DD + t] = (v - m) * rsqrtf(var + 1e-5f) * gg[t] + bb[t];
}

__global__ void ep_hidden_kernel(const float* __restrict__ W1, const float* __restrict__ b1) {
    const int lane = threadIdx.x & 31;
    const int gw = blockIdx.x * 8 + (threadIdx.x >> 5);
    const int b = gw & 31, k = gw >> 5;  // k in [0,1024)
    float v = b1[k] + wdot256(W1 + (size_t)k * DD, g_pl + (size_t)b * DD, lane);
    if (lane == 0)
        g_hid[(size_t)b * 1024 + k] = 0.5f * v * (1.0f + erff(v * 0.70710678118654752f));
}

__global__ void ep_mlp_kernel(const float* __restrict__ W2, const float* __restrict__ b2) {
    const int lane = threadIdx.x & 31;
    const int gw = blockIdx.x * 8 + (threadIdx.x >> 5);
    const int b = gw & 31, t = gw >> 5;
    float v = b2[t] + wdot1024(W2 + (size_t)t * 1024, g_hid + (size_t)b * 1024, lane);
    if (lane == 0) g_res[b * DD + t] = v + g_pl[b * DD + t];
}

// LN2: reads g_res (device symbol, device-side), writes harness d_out
__global__ void ep_ln2_kernel(const float* __restrict__ gg, const float* __restrict__ bb,
                              float* __restrict__ out) {
    const int b = blockIdx.x, t = threadIdx.x;
    __shared__ float sx[DD];
    const float v = g_res[b * DD + t];
    sx[t] = v;
    __syncthreads();
    float s1 = 0.f, s2 = 0.f;
    #pragma unroll 8
    for (int i = 0; i < DD; i++) { float x = sx[i]; s1 += x; s2 += x * x; }
    const float m = s1 * (1.0f / DD);
    const float var = s2 * (1.0f / DD) - m * m;
    out[b * DD + t] = (v - m) * rsqrtf(var + 1e-5f) * gg[t] + bb[t];
}

// ------------------------- launch -------------------------
extern "C" void kernel_launch(void* const* d_in, const int* in_sizes, int n_in,
                              void* d_out, int out_size) {
    const float* tokens = (const float*)d_in[0];
    const void*  mask   = d_in[1];
    const float* query  = (const float*)d_in[2];
    const float* Wq     = (const float*)d_in[3];
    const float* bq     = (const float*)d_in[4];
    const float* Wk     = (const float*)d_in[5];
    const float* bk     = (const float*)d_in[6];
    const float* Wv     = (const float*)d_in[7];
    const float* bv     = (const float*)d_in[8];
    const float* Wo     = (const float*)d_in[9];
    const float* bo     = (const float*)d_in[10];
    const float* ln1g   = (const float*)d_in[11];
    const float* ln1b   = (const float*)d_in[12];
    const float* W1     = (const float*)d_in[13];
    const float* b1     = (const float*)d_in[14];
    const float* W2     = (const float*)d_in[15];
    const float* b2     = (const float*)d_in[16];
    const float* ln2g   = (const float*)d_in[17];
    const float* ln2b   = (const float*)d_in[18];
    float* out = (float*)d_out;

    detect_mask_kernel<<<1, 256>>>((const unsigned*)mask);
    prep_qh_kernel<<<32, 256>>>(query, Wq, bq);
    prep_ws_kernel<<<1, 256>>>(Wk, bk);
    attn_main_kernel<<<dim3(32, 32), 256>>>(tokens, mask);
    ep_z_kernel<<<1, 256>>>();
    ep_reduce_kernel<<<128, 256>>>();
    ep_ctx_kernel<<<1024, 256>>>(Wv, bv);
    ep_attnout_kernel<<<1024, 256>>>(Wo, bo);
    ep_ln1_kernel<<<32, 256>>>(ln1g, ln1b);
    ep_hidden_kernel<<<4096, 256>>>(W1, b1);
    ep_mlp_kernel<<<1024, 256>>>(W2, b2);
    ep_ln2_kernel<<<32, 256>>>(ln2g, ln2b, out);
}

// round 5
// speedup vs baseline: 2.3574x; 1.0278x over previous
#include <cuda_runtime.h>
#include <cuda_bf16.h>
#include <math.h>

#define BB 32
#define NN 8192
#define DD 256
#define HH 8
#define NSEG 64          // segments per batch (128 tokens each)

typedef unsigned long long u64t;

// ------------------------- device scratch -------------------------
__device__ __align__(16) float g_Ws[HH * DD];               // prescaled by log2(e)
__device__ float g_c[HH];                                    // prescaled by log2(e)
__device__ __align__(16) float g_qh[DD];
__device__ __align__(16) float g_tpart[BB * NSEG * HH * DD]; // 16 MB
__device__ float g_zpart[BB * NSEG * HH];
__device__ __align__(16) float g_ctx[BB * DD];
__device__ __align__(16) float g_ao[BB * DD];
__device__ __align__(16) float g_pl[BB * DD];
__device__ __align__(16) float g_hid[BB * 4 * DD];
__device__ __align__(16) float g_res[BB * DD];
__device__ int g_mask_mode;

// ------------------------- f32x2 helpers -------------------------
__device__ __forceinline__ u64t pk(float lo, float hi) {
    u64t r; asm("mov.b64 %0,{%1,%2};" : "=l"(r) : "f"(lo), "f"(hi)); return r;
}
__device__ __forceinline__ void upk(u64t v, float& lo, float& hi) {
    asm("mov.b64 {%0,%1},%2;" : "=f"(lo), "=f"(hi) : "l"(v));
}
__device__ __forceinline__ u64t fma2(u64t a, u64t b, u64t c) {
    u64t d; asm("fma.rn.f32x2 %0,%1,%2,%3;" : "=l"(d) : "l"(a), "l"(b), "l"(c)); return d;
}
__device__ __forceinline__ u64t mul2(u64t a, u64t b) {
    u64t d; asm("mul.rn.f32x2 %0,%1,%2;" : "=l"(d) : "l"(a), "l"(b)); return d;
}
__device__ __forceinline__ u64t add2(u64t a, u64t b) {
    u64t d; asm("add.rn.f32x2 %0,%1,%2;" : "=l"(d) : "l"(a), "l"(b)); return d;
}
__device__ __forceinline__ float ex2f(float x) {
    float r; asm("ex2.approx.ftz.f32 %0,%1;" : "=f"(r) : "f"(x)); return r;
}
__device__ __forceinline__ u64t shfl64x(u64t v, int m) {
    return __shfl_xor_sync(0xffffffffu, v, m);
}

// ------------------------- mask handling -------------------------
__global__ void detect_mask_kernel(const unsigned* __restrict__ mask) {
    __shared__ int sF, sBig;
    if (threadIdx.x == 0) { sF = 0; sBig = 0; }
    __syncthreads();
    int f = 0, big = 0;
    for (int i = threadIdx.x; i < 4096; i += blockDim.x) {
        unsigned x = mask[i];
        if (x == 0x3F800000u) f++;
        else if (x > 1u) big++;
    }
    atomicAdd(&sF, f); atomicAdd(&sBig, big);
    __syncthreads();
    if (threadIdx.x == 0)
        g_mask_mode = (sF > 1000) ? 2 : ((sBig > 100) ? 0 : 1);
}

__device__ __forceinline__ float load_maskv(const void* mask, int mode, size_t idx) {
    if (mode == 0) return ((const unsigned char*)mask)[idx] ? 1.0f : 0.0f;
    if (mode == 1) return ((const int*)mask)[idx] ? 1.0f : 0.0f;
    return ((const float*)mask)[idx];
}

// ------------------------- warp dot helpers -------------------------
__device__ __forceinline__ float wdot256(const float* __restrict__ W,
                                         const float* __restrict__ x, int lane) {
    float4 w0 = *(const float4*)(W + 4 * lane);
    float4 w1 = *(const float4*)(W + 128 + 4 * lane);
    float4 x0 = *(const float4*)(x + 4 * lane);
    float4 x1 = *(const float4*)(x + 128 + 4 * lane);
    float s = w0.x * x0.x + w0.y * x0.y + w0.z * x0.z + w0.w * x0.w
            + w1.x * x1.x + w1.y * x1.y + w1.z * x1.z + w1.w * x1.w;
    #pragma unroll
    for (int m = 16; m; m >>= 1) s += __shfl_xor_sync(0xffffffffu, s, m);
    return s;
}
__device__ __forceinline__ float wdot1024(const float* __restrict__ W,
                                          const float* __restrict__ x, int lane) {
    float s = 0.f;
    #pragma unroll
    for (int c = 0; c < 8; c++) {
        float4 wv = *(const float4*)(W + c * 128 + 4 * lane);
        float4 xv = *(const float4*)(x + c * 128 + 4 * lane);
        s += wv.x * xv.x + wv.y * xv.y + wv.z * xv.z + wv.w * xv.w;
    }
    #pragma unroll
    for (int m = 16; m; m >>= 1) s += __shfl_xor_sync(0xffffffffu, s, m);
    return s;
}

// ------------------------- prep -------------------------
__global__ void prep_qh_kernel(const float* __restrict__ query, const float* __restrict__ Wq,
                               const float* __restrict__ bq) {
    const int lane = threadIdx.x & 31;
    const int j = blockIdx.x * 8 + (threadIdx.x >> 5);
    float v = bq[j] + wdot256(Wq + (size_t)j * DD, query, lane);
    if (lane == 0) g_qh[j] = v * 0.17677669529663687f; // 1/sqrt(32)
}

__global__ void prep_ws_kernel(const float* __restrict__ Wk, const float* __restrict__ bk) {
    __shared__ float q[DD];
    const int t = threadIdx.x;
    q[t] = g_qh[t];
    __syncthreads();
    const float LOG2E = 1.4426950408889634f;
    #pragma unroll
    for (int h = 0; h < HH; h++) {
        float s = 0.f;
        #pragma unroll 8
        for (int dh = 0; dh < 32; dh++)
            s += q[h * 32 + dh] * Wk[(size_t)(h * 32 + dh) * DD + t];
        g_Ws[h * DD + t] = s * LOG2E;
    }
    if (t < HH) {
        float s = 0.f;
        #pragma unroll
        for (int dh = 0; dh < 32; dh++) s += q[t * 32 + dh] * bk[t * 32 + dh];
        g_c[t] = s * LOG2E;
    }
}

// ------------------------- main fused attention pass (head-split) -------------------------
// Grid (64 seg, 32 batch), 128 threads = 4 warps = 2 stream-pairs.
// Pair p = w>>1 owns 64 contiguous tokens; warp parity hh = w&1 owns heads hh*4..hh*4+3.
// All-register butterfly score reduction; ex2 on all lanes (uniform); acc in registers.
__global__ void __launch_bounds__(128, 3) attn_main_kernel(const float* __restrict__ tokens,
                                                           const void* __restrict__ mask) {
    const int s = blockIdx.x, b = blockIdx.y;
    const int tid = threadIdx.x, w = tid >> 5, lane = tid & 31;
    const int p = w >> 1, hh = w & 1;

    __shared__ __align__(16) u64t sred[HH * 128];   // 8 KB tail buffer
    __shared__ float szbf[16];

    // Ws for my 4 heads, as f32x2 pairs
    u64t Ws2[4][4];
    #pragma unroll
    for (int hc = 0; hc < 4; hc++) {
        const int h = hh * 4 + hc;
        float4 a = *(const float4*)(g_Ws + h * DD + 4 * lane);
        float4 c = *(const float4*)(g_Ws + h * DD + 128 + 4 * lane);
        Ws2[hc][0] = pk(a.x, a.y);  Ws2[hc][1] = pk(a.z, a.w);
        Ws2[hc][2] = pk(c.x, c.y);  Ws2[hc][3] = pk(c.z, c.w);
    }
    const u64t cp0 = pk(g_c[hh * 4 + 0], g_c[hh * 4 + 1]);
    const u64t cp1 = pk(g_c[hh * 4 + 2], g_c[hh * 4 + 3]);

    u64t acc2[4][4];
    #pragma unroll
    for (int hc = 0; hc < 4; hc++)
        #pragma unroll
        for (int j = 0; j < 4; j++) acc2[hc][j] = 0ull;
    u64t zacc0 = 0ull, zacc1 = 0ull;

    const int mode = g_mask_mode;
    const size_t rowbase = (size_t)b * NN + (size_t)s * 128 + (size_t)p * 64;
    const float4* tokp = (const float4*)tokens;

    #pragma unroll 1
    for (int g = 0; g < 16; g++) {
        // load 4 tokens (pair partner loads the same rows -> L1 merge)
        float4 v[4][2];
        #pragma unroll
        for (int it = 0; it < 4; it++) {
            const size_t r = rowbase + 4 * g + it;
            v[it][0] = tokp[r * 64 + lane];
            v[it][1] = tokp[r * 64 + 32 + lane];
        }
        float mv[4];
        #pragma unroll
        for (int it = 0; it < 4; it++)
            mv[it] = load_maskv(mask, mode, rowbase + 4 * g + it);

        u64t tk[4][4];
        #pragma unroll
        for (int it = 0; it < 4; it++) {
            tk[it][0] = pk(v[it][0].x, v[it][0].y);
            tk[it][1] = pk(v[it][0].z, v[it][0].w);
            tk[it][2] = pk(v[it][1].x, v[it][1].y);
            tk[it][3] = pk(v[it][1].z, v[it][1].w);
        }

        // Stage A: per-lane partial scores for my 4 heads, packed as head-pairs
        u64t bf[8];
        #pragma unroll
        for (int it = 0; it < 4; it++) {
            float sh[4];
            #pragma unroll
            for (int hc = 0; hc < 4; hc++) {
                u64t pp = mul2(tk[it][0], Ws2[hc][0]);
                pp = fma2(tk[it][1], Ws2[hc][1], pp);
                pp = fma2(tk[it][2], Ws2[hc][2], pp);
                pp = fma2(tk[it][3], Ws2[hc][3], pp);
                float lo, hi; upk(pp, lo, hi);
                sh[hc] = lo + hi;
            }
            bf[2 * it]     = pk(sh[0], sh[1]);
            bf[2 * it + 1] = pk(sh[2], sh[3]);
        }

        // butterfly: 8 independent chains, 5 levels
        #pragma unroll
        for (int m = 1; m <= 16; m <<= 1) {
            #pragma unroll
            for (int k = 0; k < 8; k++) bf[k] = add2(bf[k], shfl64x(bf[k], m));
        }

        // bias + exp2 + mask + z + accumulate (values uniform across lanes)
        #pragma unroll
        for (int it = 0; it < 4; it++) {
            const u64t s0 = add2(bf[2 * it], cp0);
            const u64t s1 = add2(bf[2 * it + 1], cp1);
            float a0, a1, a2, a3;
            upk(s0, a0, a1); upk(s1, a2, a3);
            const float m4 = mv[it];
            const float e0 = ex2f(a0) * m4, e1 = ex2f(a1) * m4;
            const float e2 = ex2f(a2) * m4, e3 = ex2f(a3) * m4;
            zacc0 = add2(zacc0, pk(e0, e1));
            zacc1 = add2(zacc1, pk(e2, e3));
            const u64t eb0 = pk(e0, e0), eb1 = pk(e1, e1);
            const u64t eb2 = pk(e2, e2), eb3 = pk(e3, e3);
            #pragma unroll
            for (int j = 0; j < 4; j++) {
                acc2[0][j] = fma2(tk[it][j], eb0, acc2[0][j]);
                acc2[1][j] = fma2(tk[it][j], eb1, acc2[1][j]);
                acc2[2][j] = fma2(tk[it][j], eb2, acc2[2][j]);
                acc2[3][j] = fma2(tk[it][j], eb3, acc2[3][j]);
            }
        }
    }

    // ---- tail: combine the two stream-pairs (warps with same hh) ----
    // phase 1: warps 0,1 (pair 0) write; phase 2: warps 2,3 add
    #pragma unroll
    for (int phase = 0; phase < 2; phase++) {
        if (p == phase) {
            #pragma unroll
            for (int hc = 0; hc < 4; hc++) {
                #pragma unroll
                for (int j = 0; j < 4; j++) {
                    const int pairpos = (j < 2) ? (2 * lane + j) : (64 + 2 * lane + (j - 2));
                    const int idx = (hh * 4 + hc) * 128 + pairpos;
                    if (phase == 0) sred[idx] = acc2[hc][j];
                    else            sred[idx] = add2(sred[idx], acc2[hc][j]);
                }
            }
            if (lane == 0) {
                float z0, z1, z2, z3;
                upk(zacc0, z0, z1); upk(zacc1, z2, z3);
                szbf[w * 4 + 0] = z0; szbf[w * 4 + 1] = z1;
                szbf[w * 4 + 2] = z2; szbf[w * 4 + 3] = z3;
            }
        }
        __syncthreads();
    }

    // write out: 8 heads x 128 u64
    const int part = b * NSEG + s;
    u64t* tpart2 = (u64t*)g_tpart;
    #pragma unroll
    for (int k = 0; k < 8; k++)
        tpart2[(size_t)part * 1024 + k * 128 + tid] = sred[k * 128 + tid];
    if (tid < 8) {
        const int hhb = tid >> 2, j = tid & 3;
        g_zpart[part * 8 + tid] = szbf[hhb * 4 + j] + szbf[8 + hhb * 4 + j];
    }
}

// ------------------------- fused ctx kernel: z + segment-reduce + Wv dots -------------------------
// Grid 256 = (batch, head); block 256 threads.
__global__ void __launch_bounds__(256) ep_ctx_kernel(const float* __restrict__ Wv,
                                                     const float* __restrict__ bv) {
    const int b = blockIdx.x >> 3, h = blockIdx.x & 7;
    const int t = threadIdx.x, w = t >> 5, lane = t & 31;
    __shared__ float tbn[DD];
    __shared__ float szp[NSEG];
    __shared__ float zinv;

    float acc = 0.f;
    #pragma unroll 4
    for (int s = 0; s < NSEG; s++)
        acc += g_tpart[((size_t)(b * NSEG + s) * HH + h) * DD + t];
    if (t < NSEG) szp[t] = g_zpart[(b * NSEG + t) * HH + h];
    __syncthreads();
    if (t == 0) {
        float z = 0.f;
        #pragma unroll 8
        for (int i = 0; i < NSEG; i++) z += szp[i];
        zinv = 1.0f / z;
    }
    __syncthreads();
    tbn[t] = acc * zinv;
    __syncthreads();

    // 32 ctx outputs for this head: 8 warps x 4
    #pragma unroll
    for (int o = 0; o < 4; o++) {
        const int j = h * 32 + w * 4 + o;
        float v = bv[j] + wdot256(Wv + (size_t)j * DD, tbn, lane);
        if (lane == 0) g_ctx[b * DD + j] = v;
    }
}

// ------------------------- remaining epilogue -------------------------
__global__ void ep_attnout_kernel(const float* __restrict__ Wo, const float* __restrict__ bo) {
    const int lane = threadIdx.x & 31;
    const int gw = blockIdx.x * 8 + (threadIdx.x >> 5);
    const int b = gw & 31, t = gw >> 5;
    float v = bo[t] + wdot256(Wo + (size_t)t * DD, g_ctx + (size_t)b * DD, lane);
    if (lane == 0) g_ao[b * DD + t] = v;
}

__global__ void ep_ln1_kernel(const float* __restrict__ gg, const float* __restrict__ bb) {
    const int b = blockIdx.x, t = threadIdx.x;
    __shared__ float sx[DD];
    const float v = g_ao[b * DD + t];
    sx[t] = v;
    __syncthreads();
    float s1 = 0.f, s2 = 0.f;
    #pragma unroll 8
    for (int i = 0; i < DD; i++) { float x = sx[i]; s1 += x; s2 += x * x; }
    const float m = s1 * (1.0f / DD);
    const float var = s2 * (1.0f / DD) - m * m;
    g_pl[b * DD + t] = (v - m) * rsqrtf(var + 1e-5f) * gg[t] + bb[t];
}

__global__ void ep_hidden_kernel(const float* __restrict__ W1, const float* __restrict__ b1) {
    const int lane = threadIdx.x & 31;
    const int gw = blockIdx.x * 8 + (threadIdx.x >> 5);
    const int b = gw & 31, k = gw >> 5;
    float v = b1[k] + wdot256(W1 + (size_t)k * DD, g_pl + (size_t)b * DD, lane);
    if (lane == 0)
        g_hid[(size_t)b * 1024 + k] = 0.5f * v * (1.0f + erff(v * 0.70710678118654752f));
}

__global__ void ep_mlp_kernel(const float* __restrict__ W2, const float* __restrict__ b2) {
    const int lane = threadIdx.x & 31;
    const int gw = blockIdx.x * 8 + (threadIdx.x >> 5);
    const int b = gw & 31, t = gw >> 5;
    float v = b2[t] + wdot1024(W2 + (size_t)t * 1024, g_hid + (size_t)b * 1024, lane);
    if (lane == 0) g_res[b * DD + t] = v + g_pl[b * DD + t];
}

__global__ void ep_ln2_kernel(const float* __restrict__ gg, const float* __restrict__ bb,
                              float* __restrict__ out) {
    const int b = blockIdx.x, t = threadIdx.x;
    __shared__ float sx[DD];
    const float v = g_res[b * DD + t];
    sx[t] = v;
    __syncthreads();
    float s1 = 0.f, s2 = 0.f;
    #pragma unroll 8
    for (int i = 0; i < DD; i++) { float x = sx[i]; s1 += x; s2 += x * x; }
    const float m = s1 * (1.0f / DD);
    const float var = s2 * (1.0f / DD) - m * m;
    out[b * DD + t] = (v - m) * rsqrtf(var + 1e-5f) * gg[t] + bb[t];
}

// ------------------------- launch -------------------------
extern "C" void kernel_launch(void* const* d_in, const int* in_sizes, int n_in,
                              void* d_out, int out_size) {
    const float* tokens = (const float*)d_in[0];
    const void*  mask   = d_in[1];
    const float* query  = (const float*)d_in[2];
    const float* Wq     = (const float*)d_in[3];
    const float* bq     = (const float*)d_in[4];
    const float* Wk     = (const float*)d_in[5];
    const float* bk     = (const float*)d_in[6];
    const float* Wv     = (const float*)d_in[7];
    const float* bv     = (const float*)d_in[8];
    const float* Wo     = (const float*)d_in[9];
    const float* bo     = (const float*)d_in[10];
    const float* ln1g   = (const float*)d_in[11];
    const float* ln1b   = (const float*)d_in[12];
    const float* W1     = (const float*)d_in[13];
    const float* b1     = (const float*)d_in[14];
    const float* W2     = (const float*)d_in[15];
    const float* b2     = (const float*)d_in[16];
    const float* ln2g   = (const float*)d_in[17];
    const float* ln2b   = (const float*)d_in[18];
    float* out = (float*)d_out;

    detect_mask_kernel<<<1, 256>>>((const unsigned*)mask);
    prep_qh_kernel<<<32, 256>>>(query, Wq, bq);
    prep_ws_kernel<<<1, 256>>>(Wk, bk);
    attn_main_kernel<<<dim3(64, 32), 128>>>(tokens, mask);
    ep_ctx_kernel<<<256, 256>>>(Wv, bv);
    ep_attnout_kernel<<<1024, 256>>>(Wo, bo);
    ep_ln1_kernel<<<32, 256>>>(ln1g, ln1b);
    ep_hidden_kernel<<<4096, 256>>>(W1, b1);
    ep_mlp_kernel<<<1024, 256>>>(W2, b2);
    ep_ln2_kernel<<<32, 256>>>(ln2g, ln2b, out);
}

// round 6
// speedup vs baseline: 2.4500x; 1.0392x over previous
#include <cuda_runtime.h>
#include <cuda_bf16.h>
#include <math.h>

#define BB 32
#define NN 8192
#define DD 256
#define HH 8
#define NSEG 64          // segments per batch (128 tokens each)

typedef unsigned long long u64t;

// ------------------------- device scratch -------------------------
__device__ __align__(16) float g_Ws[HH * DD];               // prescaled by log2(e)
__device__ float g_c[HH];                                    // prescaled by log2(e)
__device__ __align__(16) float g_qh[DD];
__device__ __align__(16) float g_tpart[BB * NSEG * HH * DD]; // 16 MB
__device__ float g_zpart[BB * NSEG * HH];
__device__ __align__(16) float g_ctx[BB * DD];
__device__ __align__(16) float g_ao[BB * DD];
__device__ __align__(16) float g_pl[BB * DD];
__device__ __align__(16) float g_hid[BB * 4 * DD];
__device__ __align__(16) float g_res[BB * DD];
__device__ int g_mask_mode;

// ------------------------- f32x2 helpers -------------------------
__device__ __forceinline__ u64t pk(float lo, float hi) {
    u64t r; asm("mov.b64 %0,{%1,%2};" : "=l"(r) : "f"(lo), "f"(hi)); return r;
}
__device__ __forceinline__ void upk(u64t v, float& lo, float& hi) {
    asm("mov.b64 {%0,%1},%2;" : "=f"(lo), "=f"(hi) : "l"(v));
}
__device__ __forceinline__ u64t fma2(u64t a, u64t b, u64t c) {
    u64t d; asm("fma.rn.f32x2 %0,%1,%2,%3;" : "=l"(d) : "l"(a), "l"(b), "l"(c)); return d;
}
__device__ __forceinline__ u64t mul2(u64t a, u64t b) {
    u64t d; asm("mul.rn.f32x2 %0,%1,%2;" : "=l"(d) : "l"(a), "l"(b)); return d;
}
__device__ __forceinline__ u64t add2(u64t a, u64t b) {
    u64t d; asm("add.rn.f32x2 %0,%1,%2;" : "=l"(d) : "l"(a), "l"(b)); return d;
}
__device__ __forceinline__ float ex2f(float x) {
    float r; asm("ex2.approx.ftz.f32 %0,%1;" : "=f"(r) : "f"(x)); return r;
}
__device__ __forceinline__ u64t shfl64x(u64t v, int m) {
    return __shfl_xor_sync(0xffffffffu, v, m);
}

// ------------------------- mask handling -------------------------
__global__ void detect_mask_kernel(const unsigned* __restrict__ mask) {
    __shared__ int sF, sBig;
    if (threadIdx.x == 0) { sF = 0; sBig = 0; }
    __syncthreads();
    int f = 0, big = 0;
    for (int i = threadIdx.x; i < 4096; i += blockDim.x) {
        unsigned x = mask[i];
        if (x == 0x3F800000u) f++;
        else if (x > 1u) big++;
    }
    atomicAdd(&sF, f); atomicAdd(&sBig, big);
    __syncthreads();
    if (threadIdx.x == 0)
        g_mask_mode = (sF > 1000) ? 2 : ((sBig > 100) ? 0 : 1);
}

__device__ __forceinline__ float load_maskv(const void* mask, int mode, size_t idx) {
    if (mode == 0) return ((const unsigned char*)mask)[idx] ? 1.0f : 0.0f;
    if (mode == 1) return ((const int*)mask)[idx] ? 1.0f : 0.0f;
    return ((const float*)mask)[idx];
}

// ------------------------- warp dot helpers -------------------------
__device__ __forceinline__ float wdot256(const float* __restrict__ W,
                                         const float* __restrict__ x, int lane) {
    float4 w0 = *(const float4*)(W + 4 * lane);
    float4 w1 = *(const float4*)(W + 128 + 4 * lane);
    float4 x0 = *(const float4*)(x + 4 * lane);
    float4 x1 = *(const float4*)(x + 128 + 4 * lane);
    float s = w0.x * x0.x + w0.y * x0.y + w0.z * x0.z + w0.w * x0.w
            + w1.x * x1.x + w1.y * x1.y + w1.z * x1.z + w1.w * x1.w;
    #pragma unroll
    for (int m = 16; m; m >>= 1) s += __shfl_xor_sync(0xffffffffu, s, m);
    return s;
}
__device__ __forceinline__ float wdot1024(const float* __restrict__ W,
                                          const float* __restrict__ x, int lane) {
    float s = 0.f;
    #pragma unroll
    for (int c = 0; c < 8; c++) {
        float4 wv = *(const float4*)(W + c * 128 + 4 * lane);
        float4 xv = *(const float4*)(x + c * 128 + 4 * lane);
        s += wv.x * xv.x + wv.y * xv.y + wv.z * xv.z + wv.w * xv.w;
    }
    #pragma unroll
    for (int m = 16; m; m >>= 1) s += __shfl_xor_sync(0xffffffffu, s, m);
    return s;
}

// ------------------------- prep -------------------------
__global__ void prep_qh_kernel(const float* __restrict__ query, const float* __restrict__ Wq,
                               const float* __restrict__ bq) {
    const int lane = threadIdx.x & 31;
    const int j = blockIdx.x * 8 + (threadIdx.x >> 5);
    float v = bq[j] + wdot256(Wq + (size_t)j * DD, query, lane);
    if (lane == 0) g_qh[j] = v * 0.17677669529663687f; // 1/sqrt(32)
}

// one block per head
__global__ void prep_ws_kernel(const float* __restrict__ Wk, const float* __restrict__ bk) {
    const int h = blockIdx.x, t = threadIdx.x;
    __shared__ float q[32];
    if (t < 32) q[t] = g_qh[h * 32 + t];
    __syncthreads();
    const float LOG2E = 1.4426950408889634f;
    float s = 0.f;
    #pragma unroll
    for (int dh = 0; dh < 32; dh++)
        s += q[dh] * Wk[(size_t)(h * 32 + dh) * DD + t];
    g_Ws[h * DD + t] = s * LOG2E;
    if (t == 0) {
        float c = 0.f;
        #pragma unroll
        for (int dh = 0; dh < 32; dh++) c += q[dh] * bk[h * 32 + dh];
        g_c[h] = c * LOG2E;
    }
}

// ------------------------- main fused attention pass (head-split, pipelined) -------------------------
// Grid (64 seg, 32 batch), 128 threads = 4 warps = 2 stream-pairs.
// Pair p = w>>1 owns 64 contiguous tokens; warp parity hh = w&1 owns heads hh*4..hh*4+3.
// Groups of 2 tokens with prefetch-1 software pipeline.
__global__ void __launch_bounds__(128, 3) attn_main_kernel(const float* __restrict__ tokens,
                                                           const void* __restrict__ mask) {
    const int s = blockIdx.x, b = blockIdx.y;
    const int tid = threadIdx.x, w = tid >> 5, lane = tid & 31;
    const int p = w >> 1, hh = w & 1;

    __shared__ __align__(16) u64t sred[HH * 128];   // 8 KB tail buffer
    __shared__ float szbf[16];

    // Ws for my 4 heads, as f32x2 pairs
    u64t Ws2[4][4];
    #pragma unroll
    for (int hc = 0; hc < 4; hc++) {
        const int h = hh * 4 + hc;
        float4 a = *(const float4*)(g_Ws + h * DD + 4 * lane);
        float4 c = *(const float4*)(g_Ws + h * DD + 128 + 4 * lane);
        Ws2[hc][0] = pk(a.x, a.y);  Ws2[hc][1] = pk(a.z, a.w);
        Ws2[hc][2] = pk(c.x, c.y);  Ws2[hc][3] = pk(c.z, c.w);
    }
    const u64t cp0 = pk(g_c[hh * 4 + 0], g_c[hh * 4 + 1]);
    const u64t cp1 = pk(g_c[hh * 4 + 2], g_c[hh * 4 + 3]);

    u64t acc2[4][4];
    #pragma unroll
    for (int hc = 0; hc < 4; hc++)
        #pragma unroll
        for (int j = 0; j < 4; j++) acc2[hc][j] = 0ull;
    u64t zacc0 = 0ull, zacc1 = 0ull;

    const int mode = g_mask_mode;
    const size_t rowbase = (size_t)b * NN + (size_t)s * 128 + (size_t)p * 64;
    const float4* tokp = (const float4*)tokens;

    // preload group 0 (2 tokens)
    float4 cv[2][2]; float cmv[2];
    #pragma unroll
    for (int it = 0; it < 2; it++) {
        const size_t r = rowbase + it;
        cv[it][0] = tokp[r * 64 + lane];
        cv[it][1] = tokp[r * 64 + 32 + lane];
        cmv[it] = load_maskv(mask, mode, r);
    }

    #pragma unroll 1
    for (int g = 0; g < 32; g++) {
        // prefetch next group
        float4 nv[2][2]; float nmv[2];
        if (g < 31) {
            #pragma unroll
            for (int it = 0; it < 2; it++) {
                const size_t r = rowbase + 2 * (g + 1) + it;
                nv[it][0] = tokp[r * 64 + lane];
                nv[it][1] = tokp[r * 64 + 32 + lane];
                nmv[it] = load_maskv(mask, mode, r);
            }
        }

        u64t tk[2][4];
        #pragma unroll
        for (int it = 0; it < 2; it++) {
            tk[it][0] = pk(cv[it][0].x, cv[it][0].y);
            tk[it][1] = pk(cv[it][0].z, cv[it][0].w);
            tk[it][2] = pk(cv[it][1].x, cv[it][1].y);
            tk[it][3] = pk(cv[it][1].z, cv[it][1].w);
        }

        // per-lane partial scores for my 4 heads, packed as head-pairs
        u64t bf[4];
        #pragma unroll
        for (int it = 0; it < 2; it++) {
            float sh[4];
            #pragma unroll
            for (int hc = 0; hc < 4; hc++) {
                u64t pp = mul2(tk[it][0], Ws2[hc][0]);
                pp = fma2(tk[it][1], Ws2[hc][1], pp);
                pp = fma2(tk[it][2], Ws2[hc][2], pp);
                pp = fma2(tk[it][3], Ws2[hc][3], pp);
                float lo, hi; upk(pp, lo, hi);
                sh[hc] = lo + hi;
            }
            bf[2 * it]     = pk(sh[0], sh[1]);
            bf[2 * it + 1] = pk(sh[2], sh[3]);
        }

        // butterfly: 4 independent chains, 5 levels
        #pragma unroll
        for (int m = 1; m <= 16; m <<= 1) {
            #pragma unroll
            for (int k = 0; k < 4; k++) bf[k] = add2(bf[k], shfl64x(bf[k], m));
        }

        // bias + exp2 + mask + z + accumulate
        #pragma unroll
        for (int it = 0; it < 2; it++) {
            const u64t s0 = add2(bf[2 * it], cp0);
            const u64t s1 = add2(bf[2 * it + 1], cp1);
            float a0, a1, a2, a3;
            upk(s0, a0, a1); upk(s1, a2, a3);
            const float m4 = cmv[it];
            const float e0 = ex2f(a0) * m4, e1 = ex2f(a1) * m4;
            const float e2 = ex2f(a2) * m4, e3 = ex2f(a3) * m4;
            zacc0 = add2(zacc0, pk(e0, e1));
            zacc1 = add2(zacc1, pk(e2, e3));
            const u64t eb0 = pk(e0, e0), eb1 = pk(e1, e1);
            const u64t eb2 = pk(e2, e2), eb3 = pk(e3, e3);
            #pragma unroll
            for (int j = 0; j < 4; j++) {
                acc2[0][j] = fma2(tk[it][j], eb0, acc2[0][j]);
                acc2[1][j] = fma2(tk[it][j], eb1, acc2[1][j]);
                acc2[2][j] = fma2(tk[it][j], eb2, acc2[2][j]);
                acc2[3][j] = fma2(tk[it][j], eb3, acc2[3][j]);
            }
        }

        // rotate pipeline
        #pragma unroll
        for (int it = 0; it < 2; it++) {
            cv[it][0] = nv[it][0]; cv[it][1] = nv[it][1]; cmv[it] = nmv[it];
        }
    }

    // ---- tail: combine the two stream-pairs (warps with same hh) ----
    #pragma unroll
    for (int phase = 0; phase < 2; phase++) {
        if (p == phase) {
            #pragma unroll
            for (int hc = 0; hc < 4; hc++) {
                #pragma unroll
                for (int j = 0; j < 4; j++) {
                    const int pairpos = (j < 2) ? (2 * lane + j) : (64 + 2 * lane + (j - 2));
                    const int idx = (hh * 4 + hc) * 128 + pairpos;
                    if (phase == 0) sred[idx] = acc2[hc][j];
                    else            sred[idx] = add2(sred[idx], acc2[hc][j]);
                }
            }
            if (lane == 0) {
                float z0, z1, z2, z3;
                upk(zacc0, z0, z1); upk(zacc1, z2, z3);
                szbf[w * 4 + 0] = z0; szbf[w * 4 + 1] = z1;
                szbf[w * 4 + 2] = z2; szbf[w * 4 + 3] = z3;
            }
        }
        __syncthreads();
    }

    // write out: 8 heads x 128 u64
    const int part = b * NSEG + s;
    u64t* tpart2 = (u64t*)g_tpart;
    #pragma unroll
    for (int k = 0; k < 4; k++) {
        tpart2[(size_t)part * 1024 + k * 256 + tid]       = sred[k * 256 + tid];
        tpart2[(size_t)part * 1024 + k * 256 + 128 + tid] = sred[k * 256 + 128 + tid];
    }
    if (tid < 8) {
        const int hhb = tid >> 2, j = tid & 3;
        g_zpart[part * 8 + tid] = szbf[hhb * 4 + j] + szbf[8 + hhb * 4 + j];
    }
}

// ------------------------- fused ctx kernel: z + segment-reduce + Wv dots -------------------------
// Grid 256 = (batch, head); block 256 threads.
__global__ void __launch_bounds__(256) ep_ctx_kernel(const float* __restrict__ Wv,
                                                     const float* __restrict__ bv) {
    const int b = blockIdx.x >> 3, h = blockIdx.x & 7;
    const int t = threadIdx.x, w = t >> 5, lane = t & 31;
    __shared__ float tbn[DD];
    __shared__ float szp[NSEG];
    __shared__ float zinv;

    float acc = 0.f;
    #pragma unroll 8
    for (int s = 0; s < NSEG; s++)
        acc += g_tpart[((size_t)(b * NSEG + s) * HH + h) * DD + t];
    if (t < NSEG) szp[t] = g_zpart[(b * NSEG + t) * HH + h];
    __syncthreads();
    if (t == 0) {
        float z = 0.f;
        #pragma unroll 8
        for (int i = 0; i < NSEG; i++) z += szp[i];
        zinv = 1.0f / z;
    }
    __syncthreads();
    tbn[t] = acc * zinv;
    __syncthreads();

    #pragma unroll
    for (int o = 0; o < 4; o++) {
        const int j = h * 32 + w * 4 + o;
        float v = bv[j] + wdot256(Wv + (size_t)j * DD, tbn, lane);
        if (lane == 0) g_ctx[b * DD + j] = v;
    }
}

// ------------------------- remaining epilogue -------------------------
__global__ void ep_attnout_kernel(const float* __restrict__ Wo, const float* __restrict__ bo) {
    const int lane = threadIdx.x & 31;
    const int gw = blockIdx.x * 8 + (threadIdx.x >> 5);
    const int b = gw & 31, t = gw >> 5;
    float v = bo[t] + wdot256(Wo + (size_t)t * DD, g_ctx + (size_t)b * DD, lane);
    if (lane == 0) g_ao[b * DD + t] = v;
}

// fast LN: pack (x, x^2) as f32x2, warp butterfly + 8-warp smem combine
__global__ void ep_ln1_kernel(const float* __restrict__ gg, const float* __restrict__ bb) {
    const int b = blockIdx.x, t = threadIdx.x, w = t >> 5, lane = t & 31;
    __shared__ u64t sw[8];
    const float v = g_ao[b * DD + t];
    u64t pr = pk(v, v * v);
    #pragma unroll
    for (int m = 16; m; m >>= 1) pr = add2(pr, shfl64x(pr, m));
    if (lane == 0) sw[w] = pr;
    __syncthreads();
    float s1 = 0.f, s2 = 0.f;
    #pragma unroll
    for (int i = 0; i < 8; i++) { float a, q; upk(sw[i], a, q); s1 += a; s2 += q; }
    const float m = s1 * (1.0f / DD);
    const float var = s2 * (1.0f / DD) - m * m;
    g_pl[b * DD + t] = (v - m) * rsqrtf(var + 1e-5f) * gg[t] + bb[t];
}

__global__ void ep_hidden_kernel(const float* __restrict__ W1, const float* __restrict__ b1) {
    const int lane = threadIdx.x & 31;
    const int gw = blockIdx.x * 8 + (threadIdx.x >> 5);
    const int b = gw & 31, k = gw >> 5;
    float v = b1[k] + wdot256(W1 + (size_t)k * DD, g_pl + (size_t)b * DD, lane);
    if (lane == 0)
        g_hid[(size_t)b * 1024 + k] = 0.5f * v * (1.0f + erff(v * 0.70710678118654752f));
}

__global__ void ep_mlp_kernel(const float* __restrict__ W2, const float* __restrict__ b2) {
    const int lane = threadIdx.x & 31;
    const int gw = blockIdx.x * 8 + (threadIdx.x >> 5);
    const int b = gw & 31, t = gw >> 5;
    float v = b2[t] + wdot1024(W2 + (size_t)t * 1024, g_hid + (size_t)b * 1024, lane);
    if (lane == 0) g_res[b * DD + t] = v + g_pl[b * DD + t];
}

__global__ void ep_ln2_kernel(const float* __restrict__ gg, const float* __restrict__ bb,
                              float* __restrict__ out) {
    const int b = blockIdx.x, t = threadIdx.x, w = t >> 5, lane = t & 31;
    __shared__ u64t sw[8];
    const float v = g_res[b * DD + t];
    u64t pr = pk(v, v * v);
    #pragma unroll
    for (int m = 16; m; m >>= 1) pr = add2(pr, shfl64x(pr, m));
    if (lane == 0) sw[w] = pr;
    __syncthreads();
    float s1 = 0.f, s2 = 0.f;
    #pragma unroll
    for (int i = 0; i < 8; i++) { float a, q; upk(sw[i], a, q); s1 += a; s2 += q; }
    const float m = s1 * (1.0f / DD);
    const float var = s2 * (1.0f / DD) - m * m;
    out[b * DD + t] = (v - m) * rsqrtf(var + 1e-5f) * gg[t] + bb[t];
}

// ------------------------- launch -------------------------
extern "C" void kernel_launch(void* const* d_in, const int* in_sizes, int n_in,
                              void* d_out, int out_size) {
    const float* tokens = (const float*)d_in[0];
    const void*  mask   = d_in[1];
    const float* query  = (const float*)d_in[2];
    const float* Wq     = (const float*)d_in[3];
    const float* bq     = (const float*)d_in[4];
    const float* Wk     = (const float*)d_in[5];
    const float* bk     = (const float*)d_in[6];
    const float* Wv     = (const float*)d_in[7];
    const float* bv     = (const float*)d_in[8];
    const float* Wo     = (const float*)d_in[9];
    const float* bo     = (const float*)d_in[10];
    const float* ln1g   = (const float*)d_in[11];
    const float* ln1b   = (const float*)d_in[12];
    const float* W1     = (const float*)d_in[13];
    const float* b1     = (const float*)d_in[14];
    const float* W2     = (const float*)d_in[15];
    const float* b2     = (const float*)d_in[16];
    const float* ln2g   = (const float*)d_in[17];
    const float* ln2b   = (const float*)d_in[18];
    float* out = (float*)d_out;

    detect_mask_kernel<<<1, 256>>>((const unsigned*)mask);
    prep_qh_kernel<<<32, 256>>>(query, Wq, bq);
    prep_ws_kernel<<<8, 256>>>(Wk, bk);
    attn_main_kernel<<<dim3(64, 32), 128>>>(tokens, mask);
    ep_ctx_kernel<<<256, 256>>>(Wv, bv);
    ep_attnout_kernel<<<1024, 256>>>(Wo, bo);
    ep_ln1_kernel<<<32, 256>>>(ln1g, ln1b);
    ep_hidden_kernel<<<4096, 256>>>(W1, b1);
    ep_mlp_kernel<<<1024, 256>>>(W2, b2);
    ep_ln2_kernel<<<32, 256>>>(ln2g, ln2b, out);
}

// round 7
// speedup vs baseline: 2.7880x; 1.1380x over previous
#include <cuda_runtime.h>
#include <cuda_bf16.h>
#include <math.h>

#define BB 32
#define NN 8192
#define DD 256
#define HH 8
#define NSEG 64          // segments per batch (128 tokens each)

typedef unsigned long long u64t;

// ------------------------- device scratch -------------------------
__device__ __align__(16) float g_Ws[HH * DD];               // prescaled by log2(e)
__device__ float g_c[HH];                                    // prescaled by log2(e)
__device__ __align__(16) float g_qh[DD];
__device__ __align__(16) float g_tpart[BB * NSEG * HH * DD]; // 16 MB
__device__ float g_zpart[BB * NSEG * HH];
__device__ __align__(16) float g_ctx[BB * DD];
__device__ __align__(16) float g_ao[BB * DD];
__device__ __align__(16) float g_pl[BB * DD];
__device__ __align__(16) float g_hid[BB * 4 * DD];
__device__ __align__(16) float g_res[BB * DD];
__device__ int g_mask_mode;

// ------------------------- f32x2 helpers -------------------------
__device__ __forceinline__ u64t pk(float lo, float hi) {
    u64t r; asm("mov.b64 %0,{%1,%2};" : "=l"(r) : "f"(lo), "f"(hi)); return r;
}
__device__ __forceinline__ void upk(u64t v, float& lo, float& hi) {
    asm("mov.b64 {%0,%1},%2;" : "=f"(lo), "=f"(hi) : "l"(v));
}
__device__ __forceinline__ u64t fma2(u64t a, u64t b, u64t c) {
    u64t d; asm("fma.rn.f32x2 %0,%1,%2,%3;" : "=l"(d) : "l"(a), "l"(b), "l"(c)); return d;
}
__device__ __forceinline__ u64t mul2(u64t a, u64t b) {
    u64t d; asm("mul.rn.f32x2 %0,%1,%2;" : "=l"(d) : "l"(a), "l"(b)); return d;
}
__device__ __forceinline__ u64t add2(u64t a, u64t b) {
    u64t d; asm("add.rn.f32x2 %0,%1,%2;" : "=l"(d) : "l"(a), "l"(b)); return d;
}
__device__ __forceinline__ float ex2f(float x) {
    float r; asm("ex2.approx.ftz.f32 %0,%1;" : "=f"(r) : "f"(x)); return r;
}
__device__ __forceinline__ u64t shfl64x(u64t v, int m) {
    return __shfl_xor_sync(0xffffffffu, v, m);
}

// ------------------------- mask handling -------------------------
__global__ void detect_mask_kernel(const unsigned* __restrict__ mask) {
    __shared__ int sF, sBig;
    if (threadIdx.x == 0) { sF = 0; sBig = 0; }
    __syncthreads();
    int f = 0, big = 0;
    for (int i = threadIdx.x; i < 4096; i += blockDim.x) {
        unsigned x = mask[i];
        if (x == 0x3F800000u) f++;
        else if (x > 1u) big++;
    }
    atomicAdd(&sF, f); atomicAdd(&sBig, big);
    __syncthreads();
    if (threadIdx.x == 0)
        g_mask_mode = (sF > 1000) ? 2 : ((sBig > 100) ? 0 : 1);
}

__device__ __forceinline__ float load_maskv(const void* mask, int mode, size_t idx) {
    if (mode == 0) return ((const unsigned char*)mask)[idx] ? 1.0f : 0.0f;
    if (mode == 1) return ((const int*)mask)[idx] ? 1.0f : 0.0f;
    return ((const float*)mask)[idx];
}

// ------------------------- warp dot helpers -------------------------
__device__ __forceinline__ float wdot256(const float* __restrict__ W,
                                         const float* __restrict__ x, int lane) {
    float4 w0 = *(const float4*)(W + 4 * lane);
    float4 w1 = *(const float4*)(W + 128 + 4 * lane);
    float4 x0 = *(const float4*)(x + 4 * lane);
    float4 x1 = *(const float4*)(x + 128 + 4 * lane);
    float s = w0.x * x0.x + w0.y * x0.y + w0.z * x0.z + w0.w * x0.w
            + w1.x * x1.x + w1.y * x1.y + w1.z * x1.z + w1.w * x1.w;
    #pragma unroll
    for (int m = 16; m; m >>= 1) s += __shfl_xor_sync(0xffffffffu, s, m);
    return s;
}
__device__ __forceinline__ float wdot1024(const float* __restrict__ W,
                                          const float* __restrict__ x, int lane) {
    float s = 0.f;
    #pragma unroll
    for (int c = 0; c < 8; c++) {
        float4 wv = *(const float4*)(W + c * 128 + 4 * lane);
        float4 xv = *(const float4*)(x + c * 128 + 4 * lane);
        s += wv.x * xv.x + wv.y * xv.y + wv.z * xv.z + wv.w * xv.w;
    }
    #pragma unroll
    for (int m = 16; m; m >>= 1) s += __shfl_xor_sync(0xffffffffu, s, m);
    return s;
}

// ------------------------- prep -------------------------
__global__ void prep_qh_kernel(const float* __restrict__ query, const float* __restrict__ Wq,
                               const float* __restrict__ bq) {
    const int lane = threadIdx.x & 31;
    const int j = blockIdx.x * 8 + (threadIdx.x >> 5);
    float v = bq[j] + wdot256(Wq + (size_t)j * DD, query, lane);
    if (lane == 0) g_qh[j] = v * 0.17677669529663687f; // 1/sqrt(32)
}

// one block per head
__global__ void prep_ws_kernel(const float* __restrict__ Wk, const float* __restrict__ bk) {
    const int h = blockIdx.x, t = threadIdx.x;
    __shared__ float q[32];
    if (t < 32) q[t] = g_qh[h * 32 + t];
    __syncthreads();
    const float LOG2E = 1.4426950408889634f;
    float s = 0.f;
    #pragma unroll
    for (int dh = 0; dh < 32; dh++)
        s += q[dh] * Wk[(size_t)(h * 32 + dh) * DD + t];
    g_Ws[h * DD + t] = s * LOG2E;
    if (t == 0) {
        float c = 0.f;
        #pragma unroll
        for (int dh = 0; dh < 32; dh++) c += q[dh] * bk[h * 32 + dh];
        g_c[h] = c * LOG2E;
    }
}

// ------------------------- main fused attention pass (head-split, zero-cost pipeline) ----------
// Grid (64 seg, 32 batch), 128 threads = 4 warps = 2 stream-pairs.
// Pair p = w>>1 owns 64 contiguous tokens; warp parity hh = w&1 owns heads hh*4..hh*4+3.
// Group of 4 tokens. Loads for group g+1 are issued into the dead v-registers right
// after v(g) is re-paired into tk(g), BEFORE the butterfly/exp/accum math — in-warp
// latency hiding with no extra registers and no rotation movs.
__global__ void __launch_bounds__(128, 3) attn_main_kernel(const float* __restrict__ tokens,
                                                           const void* __restrict__ mask) {
    const int s = blockIdx.x, b = blockIdx.y;
    const int tid = threadIdx.x, w = tid >> 5, lane = tid & 31;
    const int p = w >> 1, hh = w & 1;

    __shared__ __align__(16) u64t sred[HH * 128];   // 8 KB tail buffer
    __shared__ float szbf[16];

    // Ws for my 4 heads, as f32x2 pairs
    u64t Ws2[4][4];
    #pragma unroll
    for (int hc = 0; hc < 4; hc++) {
        const int h = hh * 4 + hc;
        float4 a = *(const float4*)(g_Ws + h * DD + 4 * lane);
        float4 c = *(const float4*)(g_Ws + h * DD + 128 + 4 * lane);
        Ws2[hc][0] = pk(a.x, a.y);  Ws2[hc][1] = pk(a.z, a.w);
        Ws2[hc][2] = pk(c.x, c.y);  Ws2[hc][3] = pk(c.z, c.w);
    }
    const u64t cp0 = pk(g_c[hh * 4 + 0], g_c[hh * 4 + 1]);
    const u64t cp1 = pk(g_c[hh * 4 + 2], g_c[hh * 4 + 3]);

    u64t acc2[4][4];
    #pragma unroll
    for (int hc = 0; hc < 4; hc++)
        #pragma unroll
        for (int j = 0; j < 4; j++) acc2[hc][j] = 0ull;
    u64t zacc0 = 0ull, zacc1 = 0ull;

    const int mode = g_mask_mode;
    const size_t rowbase = (size_t)b * NN + (size_t)s * 128 + (size_t)p * 64;
    const float4* tokp = (const float4*)tokens;

    // preload group 0 (4 tokens)
    float4 v[4][2]; float cmv[4];
    #pragma unroll
    for (int it = 0; it < 4; it++) {
        const size_t r = rowbase + it;
        v[it][0] = tokp[r * 64 + lane];
        v[it][1] = tokp[r * 64 + 32 + lane];
        cmv[it] = load_maskv(mask, mode, r);
    }

    #pragma unroll 1
    for (int g = 0; g < 16; g++) {
        // re-pair current group into tk (register aliasing, no data movement)
        u64t tk[4][4];
        float mv[4];
        #pragma unroll
        for (int it = 0; it < 4; it++) {
            tk[it][0] = pk(v[it][0].x, v[it][0].y);
            tk[it][1] = pk(v[it][0].z, v[it][0].w);
            tk[it][2] = pk(v[it][1].x, v[it][1].y);
            tk[it][3] = pk(v[it][1].z, v[it][1].w);
            mv[it] = cmv[it];
        }

        // immediately issue next group's loads into the dead v registers
        if (g < 15) {
            #pragma unroll
            for (int it = 0; it < 4; it++) {
                const size_t r = rowbase + 4 * (g + 1) + it;
                v[it][0] = tokp[r * 64 + lane];
                v[it][1] = tokp[r * 64 + 32 + lane];
                cmv[it] = load_maskv(mask, mode, r);
            }
        }

        // per-lane partial scores for my 4 heads, packed as head-pairs
        u64t bf[8];
        #pragma unroll
        for (int it = 0; it < 4; it++) {
            float sh[4];
            #pragma unroll
            for (int hc = 0; hc < 4; hc++) {
                u64t pp = mul2(tk[it][0], Ws2[hc][0]);
                pp = fma2(tk[it][1], Ws2[hc][1], pp);
                pp = fma2(tk[it][2], Ws2[hc][2], pp);
                pp = fma2(tk[it][3], Ws2[hc][3], pp);
                float lo, hi; upk(pp, lo, hi);
                sh[hc] = lo + hi;
            }
            bf[2 * it]     = pk(sh[0], sh[1]);
            bf[2 * it + 1] = pk(sh[2], sh[3]);
        }

        // butterfly: 8 independent chains, 5 levels
        #pragma unroll
        for (int m = 1; m <= 16; m <<= 1) {
            #pragma unroll
            for (int k = 0; k < 8; k++) bf[k] = add2(bf[k], shfl64x(bf[k], m));
        }

        // bias + exp2 + mask + z + accumulate
        #pragma unroll
        for (int it = 0; it < 4; it++) {
            const u64t s0 = add2(bf[2 * it], cp0);
            const u64t s1 = add2(bf[2 * it + 1], cp1);
            float a0, a1, a2, a3;
            upk(s0, a0, a1); upk(s1, a2, a3);
            const float m4 = mv[it];
            const float e0 = ex2f(a0) * m4, e1 = ex2f(a1) * m4;
            const float e2 = ex2f(a2) * m4, e3 = ex2f(a3) * m4;
            zacc0 = add2(zacc0, pk(e0, e1));
            zacc1 = add2(zacc1, pk(e2, e3));
            const u64t eb0 = pk(e0, e0), eb1 = pk(e1, e1);
            const u64t eb2 = pk(e2, e2), eb3 = pk(e3, e3);
            #pragma unroll
            for (int j = 0; j < 4; j++) {
                acc2[0][j] = fma2(tk[it][j], eb0, acc2[0][j]);
                acc2[1][j] = fma2(tk[it][j], eb1, acc2[1][j]);
                acc2[2][j] = fma2(tk[it][j], eb2, acc2[2][j]);
                acc2[3][j] = fma2(tk[it][j], eb3, acc2[3][j]);
            }
        }
    }

    // ---- tail: combine the two stream-pairs (warps with same hh) ----
    #pragma unroll
    for (int phase = 0; phase < 2; phase++) {
        if (p == phase) {
            #pragma unroll
            for (int hc = 0; hc < 4; hc++) {
                #pragma unroll
                for (int j = 0; j < 4; j++) {
                    const int pairpos = (j < 2) ? (2 * lane + j) : (64 + 2 * lane + (j - 2));
                    const int idx = (hh * 4 + hc) * 128 + pairpos;
                    if (phase == 0) sred[idx] = acc2[hc][j];
                    else            sred[idx] = add2(sred[idx], acc2[hc][j]);
                }
            }
            if (lane == 0) {
                float z0, z1, z2, z3;
                upk(zacc0, z0, z1); upk(zacc1, z2, z3);
                szbf[w * 4 + 0] = z0; szbf[w * 4 + 1] = z1;
                szbf[w * 4 + 2] = z2; szbf[w * 4 + 3] = z3;
            }
        }
        __syncthreads();
    }

    // write out: 8 heads x 128 u64
    const int part = b * NSEG + s;
    u64t* tpart2 = (u64t*)g_tpart;
    #pragma unroll
    for (int k = 0; k < 4; k++) {
        tpart2[(size_t)part * 1024 + k * 256 + tid]       = sred[k * 256 + tid];
        tpart2[(size_t)part * 1024 + k * 256 + 128 + tid] = sred[k * 256 + 128 + tid];
    }
    if (tid < 8) {
        const int hhb = tid >> 2, j = tid & 3;
        g_zpart[part * 8 + tid] = szbf[hhb * 4 + j] + szbf[8 + hhb * 4 + j];
    }
}

// ------------------------- fused ctx kernel: z + segment-reduce + Wv dots -------------------------
// Grid 256 = (batch, head); block 256 threads.
__global__ void __launch_bounds__(256) ep_ctx_kernel(const float* __restrict__ Wv,
                                                     const float* __restrict__ bv) {
    const int b = blockIdx.x >> 3, h = blockIdx.x & 7;
    const int t = threadIdx.x, w = t >> 5, lane = t & 31;
    __shared__ float tbn[DD];
    __shared__ float szp[NSEG];
    __shared__ float zinv;

    float acc = 0.f;
    #pragma unroll 8
    for (int s = 0; s < NSEG; s++)
        acc += g_tpart[((size_t)(b * NSEG + s) * HH + h) * DD + t];
    if (t < NSEG) szp[t] = g_zpart[(b * NSEG + t) * HH + h];
    __syncthreads();
    if (t == 0) {
        float z = 0.f;
        #pragma unroll 8
        for (int i = 0; i < NSEG; i++) z += szp[i];
        zinv = 1.0f / z;
    }
    __syncthreads();
    tbn[t] = acc * zinv;
    __syncthreads();

    #pragma unroll
    for (int o = 0; o < 4; o++) {
        const int j = h * 32 + w * 4 + o;
        float v = bv[j] + wdot256(Wv + (size_t)j * DD, tbn, lane);
        if (lane == 0) g_ctx[b * DD + j] = v;
    }
}

// ------------------------- remaining epilogue -------------------------
__global__ void ep_attnout_kernel(const float* __restrict__ Wo, const float* __restrict__ bo) {
    const int lane = threadIdx.x & 31;
    const int gw = blockIdx.x * 8 + (threadIdx.x >> 5);
    const int b = gw & 31, t = gw >> 5;
    float v = bo[t] + wdot256(Wo + (size_t)t * DD, g_ctx + (size_t)b * DD, lane);
    if (lane == 0) g_ao[b * DD + t] = v;
}

// fast LN: pack (x, x^2) as f32x2, warp butterfly + 8-warp smem combine
__global__ void ep_ln1_kernel(const float* __restrict__ gg, const float* __restrict__ bb) {
    const int b = blockIdx.x, t = threadIdx.x, w = t >> 5, lane = t & 31;
    __shared__ u64t sw[8];
    const float v = g_ao[b * DD + t];
    u64t pr = pk(v, v * v);
    #pragma unroll
    for (int m = 16; m; m >>= 1) pr = add2(pr, shfl64x(pr, m));
    if (lane == 0) sw[w] = pr;
    __syncthreads();
    float s1 = 0.f, s2 = 0.f;
    #pragma unroll
    for (int i = 0; i < 8; i++) { float a, q; upk(sw[i], a, q); s1 += a; s2 += q; }
    const float m = s1 * (1.0f / DD);
    const float var = s2 * (1.0f / DD) - m * m;
    g_pl[b * DD + t] = (v - m) * rsqrtf(var + 1e-5f) * gg[t] + bb[t];
}

__global__ void ep_hidden_kernel(const float* __restrict__ W1, const float* __restrict__ b1) {
    const int lane = threadIdx.x & 31;
    const int gw = blockIdx.x * 8 + (threadIdx.x >> 5);
    const int b = gw & 31, k = gw >> 5;
    float v = b1[k] + wdot256(W1 + (size_t)k * DD, g_pl + (size_t)b * DD, lane);
    if (lane == 0)
        g_hid[(size_t)b * 1024 + k] = 0.5f * v * (1.0f + erff(v * 0.70710678118654752f));
}

__global__ void ep_mlp_kernel(const float* __restrict__ W2, const float* __restrict__ b2) {
    const int lane = threadIdx.x & 31;
    const int gw = blockIdx.x * 8 + (threadIdx.x >> 5);
    const int b = gw & 31, t = gw >> 5;
    float v = b2[t] + wdot1024(W2 + (size_t)t * 1024, g_hid + (size_t)b * 1024, lane);
    if (lane == 0) g_res[b * DD + t] = v + g_pl[b * DD + t];
}

__global__ void ep_ln2_kernel(const float* __restrict__ gg, const float* __restrict__ bb,
                              float* __restrict__ out) {
    const int b = blockIdx.x, t = threadIdx.x, w = t >> 5, lane = t & 31;
    __shared__ u64t sw[8];
    const float v = g_res[b * DD + t];
    u64t pr = pk(v, v * v);
    #pragma unroll
    for (int m = 16; m; m >>= 1) pr = add2(pr, shfl64x(pr, m));
    if (lane == 0) sw[w] = pr;
    __syncthreads();
    float s1 = 0.f, s2 = 0.f;
    #pragma unroll
    for (int i = 0; i < 8; i++) { float a, q; upk(sw[i], a, q); s1 += a; s2 += q; }
    const float m = s1 * (1.0f / DD);
    const float var = s2 * (1.0f / DD) - m * m;
    out[b * DD + t] = (v - m) * rsqrtf(var + 1e-5f) * gg[t] + bb[t];
}

// ------------------------- launch -------------------------
extern "C" void kernel_launch(void* const* d_in, const int* in_sizes, int n_in,
                              void* d_out, int out_size) {
    const float* tokens = (const float*)d_in[0];
    const void*  mask   = d_in[1];
    const float* query  = (const float*)d_in[2];
    const float* Wq     = (const float*)d_in[3];
    const float* bq     = (const float*)d_in[4];
    const float* Wk     = (const float*)d_in[5];
    const float* bk     = (const float*)d_in[6];
    const float* Wv     = (const float*)d_in[7];
    const float* bv     = (const float*)d_in[8];
    const float* Wo     = (const float*)d_in[9];
    const float* bo     = (const float*)d_in[10];
    const float* ln1g   = (const float*)d_in[11];
    const float* ln1b   = (const float*)d_in[12];
    const float* W1     = (const float*)d_in[13];
    const float* b1     = (const float*)d_in[14];
    const float* W2     = (const float*)d_in[15];
    const float* b2     = (const float*)d_in[16];
    const float* ln2g   = (const float*)d_in[17];
    const float* ln2b   = (const float*)d_in[18];
    float* out = (float*)d_out;

    detect_mask_kernel<<<1, 256>>>((const unsigned*)mask);
    prep_qh_kernel<<<32, 256>>>(query, Wq, bq);
    prep_ws_kernel<<<8, 256>>>(Wk, bk);
    attn_main_kernel<<<dim3(64, 32), 128>>>(tokens, mask);
    ep_ctx_kernel<<<256, 256>>>(Wv, bv);
    ep_attnout_kernel<<<1024, 256>>>(Wo, bo);
    ep_ln1_kernel<<<32, 256>>>(ln1g, ln1b);
    ep_hidden_kernel<<<4096, 256>>>(W1, b1);
    ep_mlp_kernel<<<1024, 256>>>(W2, b2);
    ep_ln2_kernel<<<32, 256>>>(ln2g, ln2b, out);
}